// round 10
// baseline (speedup 1.0000x reference)
#include <cuda_runtime.h>
#include <cuda_bf16.h>
#include <cstdint>

// ShapeConv via warp-level mma.sync bf16 m16n8k16 implicit GEMM.
// Round-10: warp-autonomous tiles. Each warp independently processes
// (batch, 32-o slice, 64-t window) work items: B frags loaded straight from
// global x, window norms via warp-private prefix sums. ZERO block barriers in
// the mainloop -> tensor pipe never globally pauses.

#define BB 32
#define CC 3
#define LL 8192
#define OO 128
#define KW 64
#define WW (LL - KW + 1)   /* 8129 valid windows */
#define KRED 192
#define APW 100            /* A pitch in 32-bit words (96 data + 4 pad) */
#define NBLK 296           /* 2 CTAs per SM, one wave */
#define NWRP (NBLK * 8)    /* 2368 warps */
#define WT_TOTAL (BB * 4 * 128)   /* 16384 warp-tiles */

#define A_OFF  0u          /* 128*APW bf16x2 words = 51200 B */
#define P_OFF  51200u      /* 8 warps x 128 f32 prefix arrays */
#define WS_OFF 55296u      /* 128 f32: 0.5*||w_o||^2 */
#define SMEM_BYTES 55808

__device__ unsigned int g_max[BB * OO];   // monotone-mapped maxima (zero-init)
__device__ unsigned int g_counter;        // ticket (zero-init)

__device__ __forceinline__ unsigned int f2mono(float f) {
    unsigned int u = __float_as_uint(f);
    return (u & 0x80000000u) ? ~u : (u | 0x80000000u);
}
__device__ __forceinline__ float mono2f(unsigned int m) {
    unsigned int u = (m & 0x80000000u) ? (m & 0x7fffffffu) : ~m;
    return __uint_as_float(u);
}
__device__ __forceinline__ uint32_t pack_bf2(float lo, float hi) {
    __nv_bfloat162 h = __float22bfloat162_rn(make_float2(lo, hi));
    return *(uint32_t*)&h;
}
__device__ __forceinline__ void mma_bf16(float* d, const uint32_t* a,
                                         uint32_t b0, uint32_t b1) {
    asm volatile(
        "mma.sync.aligned.m16n8k16.row.col.f32.bf16.bf16.f32 "
        "{%0,%1,%2,%3}, {%4,%5,%6,%7}, {%8,%9}, {%0,%1,%2,%3};"
        : "+f"(d[0]), "+f"(d[1]), "+f"(d[2]), "+f"(d[3])
        : "r"(a[0]), "r"(a[1]), "r"(a[2]), "r"(a[3]), "r"(b0), "r"(b1));
}
__device__ __forceinline__ void ldsm_x4(uint32_t* a, uint32_t saddr) {
    asm volatile(
        "ldmatrix.sync.aligned.m8n8.x4.shared.b16 {%0,%1,%2,%3}, [%4];"
        : "=r"(a[0]), "=r"(a[1]), "=r"(a[2]), "=r"(a[3]) : "r"(saddr));
}

// One warp-tile: conv(32 o x 64 t, K=192) + window norms + running max fold.
template <bool EDGE>
__device__ __forceinline__ void process_tile(
    const float* __restrict__ xb, int t0,
    uint32_t addrA0, uint32_t addrA1,
    float* __restrict__ Pw, int lane, int r4, int q4, float* mrow)
{
    __syncwarp();                         // Pw reads of previous tile done

    // ---- exclusive prefix of sq over [t0, t0+128) (reference's cumsum trick)
    {
        int gi = t0 + 4 * lane;
        if (EDGE) gi = min(gi, LL - 4);
        float4 c0 = *(const float4*)(xb + gi);
        float4 c1 = *(const float4*)(xb + LL + gi);
        float4 c2 = *(const float4*)(xb + 2 * LL + gi);
        float s0 = c0.x * c0.x + c1.x * c1.x + c2.x * c2.x;
        float s1 = c0.y * c0.y + c1.y * c1.y + c2.y * c2.y;
        float s2 = c0.z * c0.z + c1.z * c1.z + c2.z * c2.z;
        float s3 = c0.w * c0.w + c1.w * c1.w + c2.w * c2.w;
        float e1 = s0, e2 = s0 + s1, e3 = e2 + s2, tot = e3 + s3;
        float sc = tot;
        #pragma unroll
        for (int d = 1; d < 32; d <<= 1) {
            float t = __shfl_up_sync(0xffffffffu, sc, d);
            if (lane >= d) sc += t;
        }
        float base = sc - tot;            // exclusive warp prefix
        float4 Pv = make_float4(base, base + e1, base + e2, base + e3);
        *(float4*)(Pw + 4 * lane) = Pv;
    }
    __syncwarp();

    // ---- MMA: 32 o x 64 t, K=192; B frags straight from global x ----
    float acc[2][8][4];
    #pragma unroll
    for (int mi = 0; mi < 2; ++mi)
        #pragma unroll
        for (int nf = 0; nf < 8; ++nf)
            #pragma unroll
            for (int r = 0; r < 4; ++r) acc[mi][nf][r] = 0.f;

    const int off = t0 + r4 + 2 * q4;
    #pragma unroll
    for (int c = 0; c < CC; ++c) {
        const float* xc = xb + c * LL;
        uint32_t bb[15];
        #pragma unroll
        for (int u = 0; u < 15; ++u) {
            float v0, v1;
            if (EDGE) {
                int p = off + 8 * u;
                v0 = xc[min(p, LL - 1)];
                v1 = xc[min(p + 1, LL - 1)];
            } else {
                v0 = xc[off + 8 * u];
                v1 = xc[off + 8 * u + 1];
            }
            bb[u] = pack_bf2(v0, v1);
        }
        #pragma unroll
        for (int j = 0; j < 4; ++j) {
            const uint32_t cb = (uint32_t)(c * 32 + j * 8) << 2;
            uint32_t a[2][4];
            ldsm_x4(a[0], addrA0 + cb);
            ldsm_x4(a[1], addrA1 + cb);
            #pragma unroll
            for (int nf = 0; nf < 8; ++nf) {
                uint32_t b0 = bb[2 * j + nf], b1 = bb[2 * j + nf + 1];
                mma_bf16(acc[0][nf], a[0], b0, b1);
                mma_bf16(acc[1][nf], a[1], b0, b1);
            }
        }
    }

    // ---- epilogue: feature = D - 0.5*(P[n+64]-P[n]); fold into running max --
    #pragma unroll
    for (int nf = 0; nf < 8; ++nf) {
        const int n0 = nf * 8 + 2 * q4;
        float2 pl = *(const float2*)(Pw + n0);
        float2 ph = *(const float2*)(Pw + n0 + 64);
        float w0 = 0.5f * (ph.x - pl.x);
        float w1 = 0.5f * (ph.y - pl.y);
        if (EDGE) {
            if (t0 + n0 >= WW)     w0 = __int_as_float(0x7f800000);
            if (t0 + n0 + 1 >= WW) w1 = __int_as_float(0x7f800000);
        }
        #pragma unroll
        for (int mi = 0; mi < 2; ++mi) {
            float* d = acc[mi][nf];
            mrow[2 * mi]     = fmaxf(mrow[2 * mi],     fmaxf(d[0] - w0, d[1] - w1));
            mrow[2 * mi + 1] = fmaxf(mrow[2 * mi + 1], fmaxf(d[2] - w0, d[3] - w1));
        }
    }
}

extern "C" __global__ void __launch_bounds__(256, 2)
shapeconv_fused(const float* __restrict__ xg, const float* __restrict__ wg,
                float* __restrict__ out) {
    extern __shared__ char smem[];
    uint32_t* A_s = (uint32_t*)(smem + A_OFF);     // [128][APW] bf16x2
    float*    ws  = (float*)(smem + WS_OFF);       // [128]

    const int tid  = threadIdx.x;
    const int wid  = tid >> 5;
    const int lane = tid & 31;
    const int r4   = lane >> 2;
    const int q4   = lane & 3;

    float* Pw = (float*)(smem + P_OFF) + wid * 128;   // warp-private prefix

    // ---- A staging: warp w owns o-rows [16w,16w+16); coalesced float2 loads,
    // conflict-free STS, shuffle-reduced squared norm -> ws[o]. ----
    {
        const int o0w = wid * 16;
        #pragma unroll 4
        for (int oi = 0; oi < 16; ++oi) {
            const int o = o0w + oi;
            const float2* wp = (const float2*)(wg + o * KRED);
            float2 v0 = wp[lane], v1 = wp[lane + 32], v2 = wp[lane + 64];
            uint32_t* ap = A_s + o * APW;
            ap[lane]      = pack_bf2(v0.x, v0.y);
            ap[lane + 32] = pack_bf2(v1.x, v1.y);
            ap[lane + 64] = pack_bf2(v2.x, v2.y);
            float s = v0.x * v0.x + v0.y * v0.y + v1.x * v1.x + v1.y * v1.y
                    + v2.x * v2.x + v2.y * v2.y;
            #pragma unroll
            for (int d = 16; d; d >>= 1)
                s += __shfl_xor_sync(0xffffffffu, s, d);
            if (lane == 0) ws[o] = 0.5f * s;
        }
    }
    __syncthreads();          // the ONLY block barrier before finalize

    const uint32_t Abase = (uint32_t)__cvta_generic_to_shared(A_s);
    const uint32_t laneA = (uint32_t)(((lane & 15) * APW + ((lane >> 4) << 2)) << 2);

    // ---- warp-autonomous tile loop: widx -> (os, tw, b) ----
    const int gw = blockIdx.x * 8 + wid;
    for (int widx = gw; widx < WT_TOTAL; widx += NWRP) {
        const int os  = widx & 3;
        const int rst = widx >> 2;
        const int tw  = rst & 127;
        const int b   = rst >> 7;
        const int t0  = tw << 6;
        const float* xb = xg + b * CC * LL;

        const uint32_t addrA0 = Abase + ((uint32_t)(os * 32 * APW) << 2) + laneA;
        const uint32_t addrA1 = addrA0 + ((16 * APW) << 2);

        float mrow[4];
        #pragma unroll
        for (int r = 0; r < 4; ++r) mrow[r] = __int_as_float(0xff800000);

        if (tw == 127)
            process_tile<true>(xb, t0, addrA0, addrA1, Pw, lane, r4, q4, mrow);
        else
            process_tile<false>(xb, t0, addrA0, addrA1, Pw, lane, r4, q4, mrow);

        // ---- flush: reduce 4 lanes/row, spread-address global atomicMax ----
        #pragma unroll
        for (int r = 0; r < 4; ++r) {
            mrow[r] = fmaxf(mrow[r], __shfl_xor_sync(0xffffffffu, mrow[r], 1));
            mrow[r] = fmaxf(mrow[r], __shfl_xor_sync(0xffffffffu, mrow[r], 2));
        }
        if (q4 == 0) {
            #pragma unroll
            for (int r = 0; r < 4; ++r) {
                int row = os * 32 + (r >> 1) * 16 + (r & 1) * 8 + r4;
                atomicMax(&g_max[b * OO + row], f2mono(mrow[r]));
            }
        }
    }

    // ---- last-block inline finalize ----
    __threadfence();
    __shared__ unsigned int s_last;
    if (tid == 0)
        s_last = (atomicAdd(&g_counter, 1u) == NBLK - 1u) ? 1u : 0u;
    __syncthreads();
    if (s_last) {
        for (int idx = tid; idx < BB * OO; idx += 256) {
            int o = idx & (OO - 1);
            float v = mono2f(g_max[idx]);
            out[idx] = -2.0f * (v - ws[o]);
            g_max[idx] = 0u;               // reset for next graph replay
        }
        if (tid == 0) g_counter = 0u;
    }
}

extern "C" void kernel_launch(void* const* d_in, const int* in_sizes, int n_in,
                              void* d_out, int out_size) {
    const float* x = (const float*)d_in[0];
    const float* w = (const float*)d_in[1];
    float* out = (float*)d_out;

    cudaFuncSetAttribute(shapeconv_fused,
                         cudaFuncAttributeMaxDynamicSharedMemorySize, SMEM_BYTES);
    shapeconv_fused<<<NBLK, 256, SMEM_BYTES>>>(x, w, out);
}